// round 4
// baseline (speedup 1.0000x reference)
#include <cuda_runtime.h>
#include <mma.h>
#include <cstdint>

using namespace nvcuda;

#define Nn 50000
#define Ee 800000
#define Dd 128
#define Hh 256
#define Tt 10000
#define EPSV 1e-5f
#define STATS_BLOCKS 200
#define SCAN_BLOCKS 196

#define BM 128
#define BN 128
#define BK 16
#define LDA 20
#define LDB 136

#define NPAD 50048   // 391 * 128
#define TPAD 10112   // 79  * 128

// ---------------- scratch (static device globals; no allocation) ----------------
__device__ float g_disqrt[Nn];
__device__ int   g_cnt[Nn];
__device__ int   g_off[Nn + 1];
__device__ int   g_cursor[Nn];
__device__ int   g_bsum[SCAN_BLOCKS];
__device__ int   g_csrc[Ee];
__device__ float g_cnorm[Ee];
__device__ float g_hw[(size_t)NPAD * Hh];   // GEMM output hW (padded)
__device__ float g_agg[(size_t)Nn * Hh];    // aggregated
__device__ float g_h[(size_t)NPAD * Hh];    // activations (padded; pad rows stay 0)
__device__ float g_part[STATS_BLOCKS * 2 * Hh];
__device__ float g_stats[2 * Hh];
__device__ float g_gath[(size_t)TPAD * Hh]; // gathered train rows (padded)

// ---------------- graph preprocessing ----------------
__global__ void k_zero_cnt() {
    int i = blockIdx.x * blockDim.x + threadIdx.x;
    if (i < Nn) g_cnt[i] = 0;
}

__global__ void k_count(const int* __restrict__ row) {
    int e = blockIdx.x * blockDim.x + threadIdx.x;
    if (e < Ee) atomicAdd(&g_cnt[row[e]], 1);
}

__global__ void k_disqrt() {
    int i = blockIdx.x * blockDim.x + threadIdx.x;
    if (i < Nn) g_disqrt[i] = rsqrtf((float)g_cnt[i] + 1.0f);
}

// parallel scan, stage 1: per-block exclusive scan + block sums
__global__ void k_scan1() {
    int t = threadIdx.x, b = blockIdx.x;
    int i = b * 256 + t;
    int v = (i < Nn) ? g_cnt[i] : 0;
    int lane = t & 31, w = t >> 5;
    int x = v;
#pragma unroll
    for (int o = 1; o < 32; o <<= 1) {
        int y = __shfl_up_sync(0xffffffffu, x, o);
        if (lane >= o) x += y;
    }
    __shared__ int wsum[8];
    if (lane == 31) wsum[w] = x;
    __syncthreads();
    if (w == 0) {
        int s = (lane < 8) ? wsum[lane] : 0;
#pragma unroll
        for (int o = 1; o < 8; o <<= 1) {
            int y = __shfl_up_sync(0xffffffffu, s, o);
            if (lane >= o) s += y;
        }
        if (lane < 8) wsum[lane] = s;
    }
    __syncthreads();
    int incl = x + (w > 0 ? wsum[w - 1] : 0);
    if (i < Nn) g_off[i] = incl - v;  // exclusive within block
    if (t == 255) g_bsum[b] = incl;
}

// stage 2: exclusive scan of block sums (one block)
__global__ void k_scan2() {
    int t = threadIdx.x;
    int v = (t < SCAN_BLOCKS) ? g_bsum[t] : 0;
    int lane = t & 31, w = t >> 5;
    int x = v;
#pragma unroll
    for (int o = 1; o < 32; o <<= 1) {
        int y = __shfl_up_sync(0xffffffffu, x, o);
        if (lane >= o) x += y;
    }
    __shared__ int wsum[8];
    if (lane == 31) wsum[w] = x;
    __syncthreads();
    if (w == 0) {
        int s = (lane < 8) ? wsum[lane] : 0;
#pragma unroll
        for (int o = 1; o < 8; o <<= 1) {
            int y = __shfl_up_sync(0xffffffffu, s, o);
            if (lane >= o) s += y;
        }
        if (lane < 8) wsum[lane] = s;
    }
    __syncthreads();
    int incl = x + (w > 0 ? wsum[w - 1] : 0);
    if (t < SCAN_BLOCKS) g_bsum[t] = incl - v;  // exclusive
}

// stage 3: add block offsets, init cursor
__global__ void k_scan3() {
    int t = threadIdx.x, b = blockIdx.x;
    int i = b * 256 + t;
    if (i < Nn) {
        int off = g_off[i] + g_bsum[b];
        g_off[i] = off;
        g_cursor[i] = off;
    }
    if (i == 0) g_off[Nn] = Ee;
}

__global__ void k_scatter(const int* __restrict__ row,
                          const int* __restrict__ col) {
    int e = blockIdx.x * blockDim.x + threadIdx.x;
    if (e < Ee) {
        int d = row[e];
        int s = col[e];
        int pos = atomicAdd(&g_cursor[d], 1);
        g_csrc[pos] = s;
        g_cnorm[pos] = g_disqrt[d] * g_disqrt[s];
    }
}

// ---------------- 3xTF32 tensor-core GEMM ----------------
// C[M x 256] = A[M x K] @ B[K x 256], fp32-accurate via hi/lo tf32 split.
__device__ __forceinline__ float tf32_rn(float x) {
    asm("cvt.rna.tf32.f32 %0, %1;" : "=f"(x) : "f"(x));
    return x;
}

__global__ __launch_bounds__(256) void k_gemm_tf32(const float* __restrict__ A,
                                                   const float* __restrict__ B,
                                                   float* __restrict__ C,
                                                   int M, int K) {
    __shared__ float Ahi[BM][LDA];
    __shared__ float Alo[BM][LDA];
    __shared__ float Bhi[BK][LDB];
    __shared__ float Blo[BK][LDB];

    const int tid = threadIdx.x;
    const int warp = tid >> 5;
    const int rowBase = blockIdx.y * BM;
    const int colBase = blockIdx.x * BN;
    const int wm = warp & 3;   // 4 warps over M, 32 rows each
    const int wn = warp >> 2;  // 2 warps over N, 64 cols each

    wmma::fragment<wmma::accumulator, 16, 16, 8, float> c[2][4];
#pragma unroll
    for (int i = 0; i < 2; i++)
#pragma unroll
        for (int j = 0; j < 4; j++) wmma::fill_fragment(c[i][j], 0.0f);

    const int ar = tid >> 2;           // 0..63
    const int ak = (tid & 3) * 4;      // 0,4,8,12
    const int br = tid >> 5;           // 0..7
    const int bc = (tid & 31) * 4;     // 0..124

    for (int k0 = 0; k0 < K; k0 += BK) {
        // A tile: 128x16, two rows per thread
#pragma unroll
        for (int rr = 0; rr < 2; rr++) {
            int lrow = ar + rr * 64;
            int grow = rowBase + lrow;
            float4 v = make_float4(0.f, 0.f, 0.f, 0.f);
            if (grow < M) v = *(const float4*)(A + (size_t)grow * K + k0 + ak);
            float h0 = tf32_rn(v.x), h1 = tf32_rn(v.y), h2 = tf32_rn(v.z), h3 = tf32_rn(v.w);
            Ahi[lrow][ak + 0] = h0; Alo[lrow][ak + 0] = tf32_rn(v.x - h0);
            Ahi[lrow][ak + 1] = h1; Alo[lrow][ak + 1] = tf32_rn(v.y - h1);
            Ahi[lrow][ak + 2] = h2; Alo[lrow][ak + 2] = tf32_rn(v.z - h2);
            Ahi[lrow][ak + 3] = h3; Alo[lrow][ak + 3] = tf32_rn(v.w - h3);
        }
        // B tile: 16x128, two rows per thread
#pragma unroll
        for (int rr = 0; rr < 2; rr++) {
            int lrow = br + rr * 8;
            float4 v = *(const float4*)(B + (size_t)(k0 + lrow) * Hh + colBase + bc);
            float h0 = tf32_rn(v.x), h1 = tf32_rn(v.y), h2 = tf32_rn(v.z), h3 = tf32_rn(v.w);
            Bhi[lrow][bc + 0] = h0; Blo[lrow][bc + 0] = tf32_rn(v.x - h0);
            Bhi[lrow][bc + 1] = h1; Blo[lrow][bc + 1] = tf32_rn(v.y - h1);
            Bhi[lrow][bc + 2] = h2; Blo[lrow][bc + 2] = tf32_rn(v.z - h2);
            Bhi[lrow][bc + 3] = h3; Blo[lrow][bc + 3] = tf32_rn(v.w - h3);
        }
        __syncthreads();

#pragma unroll
        for (int ks = 0; ks < BK; ks += 8) {
            wmma::fragment<wmma::matrix_a, 16, 16, 8, wmma::precision::tf32, wmma::row_major> ahi[2], alo[2];
            wmma::fragment<wmma::matrix_b, 16, 16, 8, wmma::precision::tf32, wmma::row_major> bhi[4], blo[4];
#pragma unroll
            for (int i = 0; i < 2; i++) {
                wmma::load_matrix_sync(ahi[i], &Ahi[wm * 32 + i * 16][ks], LDA);
                wmma::load_matrix_sync(alo[i], &Alo[wm * 32 + i * 16][ks], LDA);
            }
#pragma unroll
            for (int j = 0; j < 4; j++) {
                wmma::load_matrix_sync(bhi[j], &Bhi[ks][wn * 64 + j * 16], LDB);
                wmma::load_matrix_sync(blo[j], &Blo[ks][wn * 64 + j * 16], LDB);
            }
#pragma unroll
            for (int i = 0; i < 2; i++)
#pragma unroll
                for (int j = 0; j < 4; j++) {
                    wmma::mma_sync(c[i][j], ahi[i], bhi[j], c[i][j]);
                    wmma::mma_sync(c[i][j], alo[i], bhi[j], c[i][j]);
                    wmma::mma_sync(c[i][j], ahi[i], blo[j], c[i][j]);
                }
        }
        __syncthreads();
    }

#pragma unroll
    for (int i = 0; i < 2; i++)
#pragma unroll
        for (int j = 0; j < 4; j++) {
            int grow = rowBase + wm * 32 + i * 16;
            wmma::store_matrix_sync(C + (size_t)grow * Hh + colBase + wn * 64 + j * 16,
                                    c[i][j], Hh, wmma::mem_row_major);
        }
}

// ---------------- aggregation: warp per destination node ----------------
__global__ void k_agg() {
    int warp = (blockIdx.x * blockDim.x + threadIdx.x) >> 5;
    int lane = threadIdx.x & 31;
    if (warp >= Nn) return;
    int i = warp;

    const float4* hw4 = (const float4*)g_hw;
    float dsq = g_disqrt[i];
    float sl = dsq * dsq;  // self-loop norm

    float4 v0 = hw4[(size_t)i * 64 + lane];
    float4 v1 = hw4[(size_t)i * 64 + 32 + lane];
    float4 acc0 = make_float4(v0.x * sl, v0.y * sl, v0.z * sl, v0.w * sl);
    float4 acc1 = make_float4(v1.x * sl, v1.y * sl, v1.z * sl, v1.w * sl);

    int e0 = g_off[i];
    int e1 = g_off[i + 1];
    for (int e = e0; e < e1; e++) {
        int s = g_csrc[e];
        float nm = g_cnorm[e];
        float4 w0 = hw4[(size_t)s * 64 + lane];
        float4 w1 = hw4[(size_t)s * 64 + 32 + lane];
        acc0.x = fmaf(w0.x, nm, acc0.x);
        acc0.y = fmaf(w0.y, nm, acc0.y);
        acc0.z = fmaf(w0.z, nm, acc0.z);
        acc0.w = fmaf(w0.w, nm, acc0.w);
        acc1.x = fmaf(w1.x, nm, acc1.x);
        acc1.y = fmaf(w1.y, nm, acc1.y);
        acc1.z = fmaf(w1.z, nm, acc1.z);
        acc1.w = fmaf(w1.w, nm, acc1.w);
    }
    float4* a4 = (float4*)g_agg;
    a4[(size_t)i * 64 + lane] = acc0;
    a4[(size_t)i * 64 + 32 + lane] = acc1;
}

// ---------------- BatchNorm (deterministic two-stage stats) ----------------
__global__ void k_stats_partial() {
    int j = threadIdx.x;  // 0..255
    float s = 0.f, s2 = 0.f;
    for (int r = blockIdx.x; r < Nn; r += gridDim.x) {
        float v = g_agg[(size_t)r * Hh + j];
        s += v;
        s2 += v * v;
    }
    g_part[blockIdx.x * 2 * Hh + j] = s;
    g_part[blockIdx.x * 2 * Hh + Hh + j] = s2;
}

__global__ void k_stats_reduce() {
    int j = blockIdx.x * blockDim.x + threadIdx.x;
    if (j >= 2 * Hh) return;
    float s = 0.f;
    for (int b = 0; b < STATS_BLOCKS; b++) s += g_part[b * 2 * Hh + j];
    g_stats[j] = s;
}

__global__ void k_bn_relu(const float* __restrict__ gamma,
                          const float* __restrict__ beta) {
    int idx = blockIdx.x * blockDim.x + threadIdx.x;
    const int total = Nn * 64;
    if (idx >= total) return;
    int c4 = (idx & 63) * 4;
    int r = idx >> 6;
    const float4* a4 = (const float4*)g_agg;
    float4 v = a4[idx];
    float out[4];
    float in[4] = {v.x, v.y, v.z, v.w};
    const float invN = 1.0f / (float)Nn;
#pragma unroll
    for (int q = 0; q < 4; q++) {
        int j = c4 + q;
        float mu = g_stats[j] * invN;
        float var = fmaxf(g_stats[Hh + j] * invN - mu * mu, 0.0f);
        float y = (in[q] - mu) * rsqrtf(var + EPSV) * gamma[j] + beta[j];
        out[q] = fmaxf(y, 0.0f);
    }
    ((float4*)g_h)[(size_t)r * 64 + (idx & 63)] = make_float4(out[0], out[1], out[2], out[3]);
}

// ---------------- final layers ----------------
__global__ void k_gather(const int* __restrict__ train) {
    int idx = blockIdx.x * blockDim.x + threadIdx.x;
    const int total = Tt * 64;
    if (idx >= total) return;
    int t = idx >> 6;
    int c = idx & 63;
    int node = train[t];
    ((float4*)g_gath)[idx] = ((const float4*)g_h)[(size_t)node * 64 + c];
}

__global__ void k_out(const float* __restrict__ bl,
                      const float* __restrict__ Wf,
                      const float* __restrict__ bf,
                      float* __restrict__ out) {
    int warp = (blockIdx.x * blockDim.x + threadIdx.x) >> 5;
    int lane = threadIdx.x & 31;
    if (warp >= Tt) return;
    float acc = 0.f;
    const float* hp = g_hw + (size_t)warp * Hh;
#pragma unroll
    for (int j0 = 0; j0 < Hh; j0 += 32) {
        int j = j0 + lane;
        float v = fmaxf(hp[j] + bl[j], 0.0f);
        acc = fmaf(v, Wf[j], acc);
    }
#pragma unroll
    for (int o = 16; o > 0; o >>= 1) acc += __shfl_xor_sync(0xffffffffu, acc, o);
    if (lane == 0) out[warp] = acc + bf[0];
}

// ---------------- launch ----------------
extern "C" void kernel_launch(void* const* d_in, const int* in_sizes, int n_in,
                              void* d_out, int out_size) {
    const float* x = (const float*)d_in[0];
    const int* ei = (const int*)d_in[1];     // int32 (JAX x64 disabled)
    const int* train = (const int*)d_in[2];  // int32
    const float* W1 = (const float*)d_in[3];
    const float* W2 = (const float*)d_in[5];
    const float* W3 = (const float*)d_in[7];
    const float* g1 = (const float*)d_in[9];
    const float* be1 = (const float*)d_in[10];
    const float* g2 = (const float*)d_in[11];
    const float* be2 = (const float*)d_in[12];
    const float* g3 = (const float*)d_in[13];
    const float* be3 = (const float*)d_in[14];
    const float* Wl = (const float*)d_in[15];
    const float* bl = (const float*)d_in[16];
    const float* Wf = (const float*)d_in[17];
    const float* bf = (const float*)d_in[18];
    float* out = (float*)d_out;

    const int* row = ei;
    const int* col = ei + Ee;

    float* p_hw = nullptr;
    float* p_h = nullptr;
    float* p_gath = nullptr;
    cudaGetSymbolAddress((void**)&p_hw, g_hw);
    cudaGetSymbolAddress((void**)&p_h, g_h);
    cudaGetSymbolAddress((void**)&p_gath, g_gath);

    // ---- graph preprocessing ----
    k_zero_cnt<<<(Nn + 255) / 256, 256>>>();
    k_count<<<(Ee + 255) / 256, 256>>>(row);
    k_disqrt<<<(Nn + 255) / 256, 256>>>();
    k_scan1<<<SCAN_BLOCKS, 256>>>();
    k_scan2<<<1, 256>>>();
    k_scan3<<<SCAN_BLOCKS, 256>>>();
    k_scatter<<<(Ee + 255) / 256, 256>>>(row, col);

    dim3 gemm_grid(2, NPAD / 128);
    const int agg_blocks = (Nn * 32 + 255) / 256;
    const int bn_blocks = (Nn * 64 + 255) / 256;

    // ---- layer 1 ----
    k_gemm_tf32<<<gemm_grid, 256>>>(x, W1, p_hw, Nn, Dd);
    k_agg<<<agg_blocks, 256>>>();
    k_stats_partial<<<STATS_BLOCKS, 256>>>();
    k_stats_reduce<<<1, 512>>>();
    k_bn_relu<<<bn_blocks, 256>>>(g1, be1);

    // ---- layer 2 ----
    k_gemm_tf32<<<gemm_grid, 256>>>(p_h, W2, p_hw, NPAD, Hh);
    k_agg<<<agg_blocks, 256>>>();
    k_stats_partial<<<STATS_BLOCKS, 256>>>();
    k_stats_reduce<<<1, 512>>>();
    k_bn_relu<<<bn_blocks, 256>>>(g2, be2);

    // ---- layer 3 ----
    k_gemm_tf32<<<gemm_grid, 256>>>(p_h, W3, p_hw, NPAD, Hh);
    k_agg<<<agg_blocks, 256>>>();
    k_stats_partial<<<STATS_BLOCKS, 256>>>();
    k_stats_reduce<<<1, 512>>>();
    k_bn_relu<<<bn_blocks, 256>>>(g3, be3);

    // ---- head: gather train rows, Wl GEMM, fused relu + Wf dot ----
    k_gather<<<(Tt * 64 + 255) / 256, 256>>>(train);
    dim3 head_grid(2, TPAD / 128);
    k_gemm_tf32<<<head_grid, 256>>>(p_gath, Wl, p_hw, TPAD, Hh);
    k_out<<<(Tt * 32 + 255) / 256, 256>>>(bl, Wf, bf, out);
}

// round 6
// speedup vs baseline: 1.3414x; 1.3414x over previous
#include <cuda_runtime.h>
#include <mma.h>
#include <cstdint>

using namespace nvcuda;

#define Nn 50000
#define Ee 800000
#define Dd 128
#define Hh 256
#define Tt 10000
#define EPSV 1e-5f
#define STATS_BLOCKS 200
#define SCAN_BLOCKS 196
#define NPAD 50048   // 391 * 128

// ---------------- scratch ----------------
__device__ float g_disqrt[Nn];
__device__ int   g_cnt[Nn];
__device__ int   g_off[Nn + 1];
__device__ int   g_cursor[Nn];
__device__ int   g_bsum[SCAN_BLOCKS];
__device__ int   g_csrc[Ee];
__device__ float g_cnorm[Ee];
__device__ float g_aggx[(size_t)Nn * Dd];   // aggregated input x (layer 1)
__device__ float g_agg[(size_t)Nn * Hh];    // aggregated activations (layers 2,3)
__device__ float g_hw[(size_t)NPAD * Hh];   // GEMM output
__device__ float g_h[(size_t)Nn * Hh];      // post-BN activations
__device__ float g_part[STATS_BLOCKS * 2 * Hh];
__device__ float g_stats[2 * Hh];
__device__ float g_gath[(size_t)Tt * Hh];

// ---------------- helpers ----------------
__device__ __forceinline__ float tf32_rn(float x) {
    asm("cvt.rna.tf32.f32 %0, %1;" : "=f"(x) : "f"(x));
    return x;
}
__device__ __forceinline__ void cp16(uint32_t dst, const void* src, int bytes) {
    asm volatile("cp.async.cg.shared.global [%0], [%1], 16, %2;"
                 :: "r"(dst), "l"(src), "r"(bytes) : "memory");
}
#define CP_COMMIT() asm volatile("cp.async.commit_group;" ::: "memory")
#define CP_WAIT1()  asm volatile("cp.async.wait_group 1;" ::: "memory")
#define CP_WAIT0()  asm volatile("cp.async.wait_group 0;" ::: "memory")

// ---------------- graph preprocessing ----------------
__global__ void k_zero_cnt() {
    int i = blockIdx.x * blockDim.x + threadIdx.x;
    if (i < Nn) g_cnt[i] = 0;
}
__global__ void k_count(const int* __restrict__ row) {
    int e = blockIdx.x * blockDim.x + threadIdx.x;
    if (e < Ee) atomicAdd(&g_cnt[row[e]], 1);
}
__global__ void k_disqrt() {
    int i = blockIdx.x * blockDim.x + threadIdx.x;
    if (i < Nn) g_disqrt[i] = rsqrtf((float)g_cnt[i] + 1.0f);
}
__global__ void k_scan1() {
    int t = threadIdx.x, b = blockIdx.x;
    int i = b * 256 + t;
    int v = (i < Nn) ? g_cnt[i] : 0;
    int lane = t & 31, w = t >> 5;
    int x = v;
#pragma unroll
    for (int o = 1; o < 32; o <<= 1) {
        int y = __shfl_up_sync(0xffffffffu, x, o);
        if (lane >= o) x += y;
    }
    __shared__ int wsum[8];
    if (lane == 31) wsum[w] = x;
    __syncthreads();
    if (w == 0) {
        int s = (lane < 8) ? wsum[lane] : 0;
#pragma unroll
        for (int o = 1; o < 8; o <<= 1) {
            int y = __shfl_up_sync(0xffffffffu, s, o);
            if (lane >= o) s += y;
        }
        if (lane < 8) wsum[lane] = s;
    }
    __syncthreads();
    int incl = x + (w > 0 ? wsum[w - 1] : 0);
    if (i < Nn) g_off[i] = incl - v;
    if (t == 255) g_bsum[b] = incl;
}
__global__ void k_scan2() {
    int t = threadIdx.x;
    int v = (t < SCAN_BLOCKS) ? g_bsum[t] : 0;
    int lane = t & 31, w = t >> 5;
    int x = v;
#pragma unroll
    for (int o = 1; o < 32; o <<= 1) {
        int y = __shfl_up_sync(0xffffffffu, x, o);
        if (lane >= o) x += y;
    }
    __shared__ int wsum[8];
    if (lane == 31) wsum[w] = x;
    __syncthreads();
    if (w == 0) {
        int s = (lane < 8) ? wsum[lane] : 0;
#pragma unroll
        for (int o = 1; o < 8; o <<= 1) {
            int y = __shfl_up_sync(0xffffffffu, s, o);
            if (lane >= o) s += y;
        }
        if (lane < 8) wsum[lane] = s;
    }
    __syncthreads();
    int incl = x + (w > 0 ? wsum[w - 1] : 0);
    if (t < SCAN_BLOCKS) g_bsum[t] = incl - v;
}
__global__ void k_scan3() {
    int t = threadIdx.x, b = blockIdx.x;
    int i = b * 256 + t;
    if (i < Nn) {
        int off = g_off[i] + g_bsum[b];
        g_off[i] = off;
        g_cursor[i] = off;
    }
    if (i == 0) g_off[Nn] = Ee;
}
__global__ void k_scatter(const int* __restrict__ row, const int* __restrict__ col) {
    int e = blockIdx.x * blockDim.x + threadIdx.x;
    if (e < Ee) {
        int d = row[e];
        int s = col[e];
        int pos = atomicAdd(&g_cursor[d], 1);
        g_csrc[pos] = s;
        g_cnorm[pos] = g_disqrt[d] * g_disqrt[s];
    }
}

// ---------------- 3xTF32 wmma GEMM with cp.async double buffering ----------------
// C[M x 256] = A[M x K] @ B[K x 256]; B is the raw weight matrix (row-major [K][256]).
#define LDA 20
#define LDB 132

using FragA = wmma::fragment<wmma::matrix_a, 16, 16, 8, wmma::precision::tf32, wmma::row_major>;
using FragB = wmma::fragment<wmma::matrix_b, 16, 16, 8, wmma::precision::tf32, wmma::row_major>;
using FragC = wmma::fragment<wmma::accumulator, 16, 16, 8, float>;

template <class F>
__device__ __forceinline__ void split_frag(const F& f, F& hi, F& lo) {
#pragma unroll
    for (int e = 0; e < f.num_elements; e++) {
        float h = tf32_rn(f.x[e]);
        hi.x[e] = h;
        lo.x[e] = tf32_rn(f.x[e] - h);
    }
}

__global__ __launch_bounds__(256) void k_gemm(const float* __restrict__ A,
                                              const float* __restrict__ B,
                                              float* __restrict__ C,
                                              int M, int K) {
    __shared__ float As[2][128][LDA];
    __shared__ float Bs[2][16][LDB];

    const int tid = threadIdx.x;
    const int warp = tid >> 5;
    const int rowBase = blockIdx.y * 128;
    const int colBase = blockIdx.x * 128;
    const int wm = warp & 3;   // 4 warps over M (32 rows each)
    const int wn = warp >> 2;  // 2 warps over N (64 cols each)

    FragC c[2][4];
#pragma unroll
    for (int i = 0; i < 2; i++)
#pragma unroll
        for (int j = 0; j < 4; j++) wmma::fill_fragment(c[i][j], 0.0f);

    // cp.async mappings (per thread: 2 A-chunks + 2 B-chunks of 16B)
    const int NC = K >> 4;

    auto load_stage = [&](int buf, int k0) {
#pragma unroll
        for (int t = 0; t < 2; t++) {
            int id = tid + t * 256;          // 0..511
            int r = id >> 2;                 // 0..127
            int kq = (id & 3) * 4;           // 0,4,8,12
            int grow = rowBase + r;
            uint32_t dst = (uint32_t)__cvta_generic_to_shared(&As[buf][r][kq]);
            const float* src = A + (size_t)(grow < M ? grow : 0) * K + k0 + kq;
            cp16(dst, src, grow < M ? 16 : 0);
        }
#pragma unroll
        for (int t = 0; t < 2; t++) {
            int id = tid + t * 256;          // 0..511
            int kr = id >> 5;                // 0..15
            int nq = (id & 31) * 4;          // 0..124
            uint32_t dst = (uint32_t)__cvta_generic_to_shared(&Bs[buf][kr][nq]);
            const float* src = B + (size_t)(k0 + kr) * Hh + colBase + nq;
            cp16(dst, src, 16);
        }
    };

    load_stage(0, 0);
    CP_COMMIT();

    for (int cidx = 0; cidx < NC; cidx++) {
        int buf = cidx & 1;
        if (cidx + 1 < NC) {
            load_stage(buf ^ 1, (cidx + 1) << 4);
            CP_COMMIT();
            CP_WAIT1();
        } else {
            CP_WAIT0();
        }
        __syncthreads();

#pragma unroll
        for (int ks = 0; ks < 2; ks++) {
            FragA af, ahi[2], alo[2];
            FragB bf, bhi[4], blo[4];
#pragma unroll
            for (int i = 0; i < 2; i++) {
                wmma::load_matrix_sync(af, &As[buf][wm * 32 + i * 16][ks * 8], LDA);
                split_frag(af, ahi[i], alo[i]);
            }
#pragma unroll
            for (int j = 0; j < 4; j++) {
                wmma::load_matrix_sync(bf, &Bs[buf][ks * 8][wn * 64 + j * 16], LDB);
                split_frag(bf, bhi[j], blo[j]);
            }
#pragma unroll
            for (int i = 0; i < 2; i++)
#pragma unroll
                for (int j = 0; j < 4; j++) {
                    wmma::mma_sync(c[i][j], ahi[i], bhi[j], c[i][j]);
                    wmma::mma_sync(c[i][j], alo[i], bhi[j], c[i][j]);
                    wmma::mma_sync(c[i][j], ahi[i], blo[j], c[i][j]);
                }
        }
        __syncthreads();
    }

#pragma unroll
    for (int i = 0; i < 2; i++)
#pragma unroll
        for (int j = 0; j < 4; j++) {
            int grow = rowBase + wm * 32 + i * 16;  // C buffer padded to NPAD rows
            wmma::store_matrix_sync(C + (size_t)grow * Hh + colBase + wn * 64 + j * 16,
                                    c[i][j], Hh, wmma::mem_row_major);
        }
}

// ---------------- aggregation: warp per destination node (templated width) ----------------
template <int W4>  // float4s per row: 32 (128 floats) or 64 (256 floats)
__global__ void k_agg_t(const float* __restrict__ src, float* __restrict__ dst) {
    int warp = (blockIdx.x * blockDim.x + threadIdx.x) >> 5;
    int lane = threadIdx.x & 31;
    if (warp >= Nn) return;
    const float4* s4 = (const float4*)src;
    float dsq = g_disqrt[warp];
    float sl = dsq * dsq;

    float4 acc[W4 / 32];
#pragma unroll
    for (int q = 0; q < W4 / 32; q++) {
        float4 v = s4[(size_t)warp * W4 + q * 32 + lane];
        acc[q] = make_float4(v.x * sl, v.y * sl, v.z * sl, v.w * sl);
    }
    int e0 = g_off[warp], e1 = g_off[warp + 1];
    for (int e = e0; e < e1; e++) {
        int s = g_csrc[e];
        float nm = g_cnorm[e];
#pragma unroll
        for (int q = 0; q < W4 / 32; q++) {
            float4 v = s4[(size_t)s * W4 + q * 32 + lane];
            acc[q].x = fmaf(v.x, nm, acc[q].x);
            acc[q].y = fmaf(v.y, nm, acc[q].y);
            acc[q].z = fmaf(v.z, nm, acc[q].z);
            acc[q].w = fmaf(v.w, nm, acc[q].w);
        }
    }
    float4* d4 = (float4*)dst;
#pragma unroll
    for (int q = 0; q < W4 / 32; q++) d4[(size_t)warp * W4 + q * 32 + lane] = acc[q];
}

// ---------------- BatchNorm (on g_hw) ----------------
__global__ void k_stats_partial() {
    int j = threadIdx.x;
    float s = 0.f, s2 = 0.f;
    for (int r = blockIdx.x; r < Nn; r += gridDim.x) {
        float v = g_hw[(size_t)r * Hh + j];
        s += v;
        s2 += v * v;
    }
    g_part[blockIdx.x * 2 * Hh + j] = s;
    g_part[blockIdx.x * 2 * Hh + Hh + j] = s2;
}
__global__ void k_stats_reduce() {
    int j = blockIdx.x * blockDim.x + threadIdx.x;
    if (j >= 2 * Hh) return;
    float s = 0.f;
    for (int b = 0; b < STATS_BLOCKS; b++) s += g_part[b * 2 * Hh + j];
    g_stats[j] = s;
}
__global__ void k_bn_relu(const float* __restrict__ gamma, const float* __restrict__ beta) {
    int idx = blockIdx.x * blockDim.x + threadIdx.x;
    const int total = Nn * 64;
    if (idx >= total) return;
    int c4 = (idx & 63) * 4;
    float4 v = ((const float4*)g_hw)[idx];
    float out[4];
    float in[4] = {v.x, v.y, v.z, v.w};
    const float invN = 1.0f / (float)Nn;
#pragma unroll
    for (int q = 0; q < 4; q++) {
        int j = c4 + q;
        float mu = g_stats[j] * invN;
        float var = fmaxf(g_stats[Hh + j] * invN - mu * mu, 0.0f);
        float y = (in[q] - mu) * rsqrtf(var + EPSV) * gamma[j] + beta[j];
        out[q] = fmaxf(y, 0.0f);
    }
    ((float4*)g_h)[idx] = make_float4(out[0], out[1], out[2], out[3]);
}

// ---------------- final layers ----------------
__global__ void k_gather(const int* __restrict__ train) {
    int idx = blockIdx.x * blockDim.x + threadIdx.x;
    const int total = Tt * 64;
    if (idx >= total) return;
    int t = idx >> 6;
    int c = idx & 63;
    int node = train[t];
    ((float4*)g_gath)[idx] = ((const float4*)g_h)[(size_t)node * 64 + c];
}
__global__ void k_out(const float* __restrict__ bl, const float* __restrict__ Wf,
                      const float* __restrict__ bf, float* __restrict__ out) {
    int warp = (blockIdx.x * blockDim.x + threadIdx.x) >> 5;
    int lane = threadIdx.x & 31;
    if (warp >= Tt) return;
    float acc = 0.f;
    const float* hp = g_hw + (size_t)warp * Hh;
#pragma unroll
    for (int j0 = 0; j0 < Hh; j0 += 32) {
        int j = j0 + lane;
        float v = fmaxf(hp[j] + bl[j], 0.0f);
        acc = fmaf(v, Wf[j], acc);
    }
#pragma unroll
    for (int o = 16; o > 0; o >>= 1) acc += __shfl_xor_sync(0xffffffffu, acc, o);
    if (lane == 0) out[warp] = acc + bf[0];
}

// ---------------- launch ----------------
extern "C" void kernel_launch(void* const* d_in, const int* in_sizes, int n_in,
                              void* d_out, int out_size) {
    const float* x = (const float*)d_in[0];
    const int* ei = (const int*)d_in[1];
    const int* train = (const int*)d_in[2];
    const float* W1 = (const float*)d_in[3];
    const float* W2 = (const float*)d_in[5];
    const float* W3 = (const float*)d_in[7];
    const float* g1 = (const float*)d_in[9];
    const float* be1 = (const float*)d_in[10];
    const float* g2 = (const float*)d_in[11];
    const float* be2 = (const float*)d_in[12];
    const float* g3 = (const float*)d_in[13];
    const float* be3 = (const float*)d_in[14];
    const float* Wl = (const float*)d_in[15];
    const float* bl = (const float*)d_in[16];
    const float* Wf = (const float*)d_in[17];
    const float* bf = (const float*)d_in[18];
    float* out = (float*)d_out;

    const int* row = ei;
    const int* col = ei + Ee;

    float *p_hw, *p_h, *p_gath, *p_agg, *p_aggx;
    cudaGetSymbolAddress((void**)&p_hw, g_hw);
    cudaGetSymbolAddress((void**)&p_h, g_h);
    cudaGetSymbolAddress((void**)&p_gath, g_gath);
    cudaGetSymbolAddress((void**)&p_agg, g_agg);
    cudaGetSymbolAddress((void**)&p_aggx, g_aggx);

    // ---- graph preprocessing ----
    k_zero_cnt<<<(Nn + 255) / 256, 256>>>();
    k_count<<<(Ee + 255) / 256, 256>>>(row);
    k_disqrt<<<(Nn + 255) / 256, 256>>>();
    k_scan1<<<SCAN_BLOCKS, 256>>>();
    k_scan2<<<1, 256>>>();
    k_scan3<<<SCAN_BLOCKS, 256>>>();
    k_scatter<<<(Ee + 255) / 256, 256>>>(row, col);

    const int agg_blocks = (Nn * 32 + 255) / 256;
    const int bn_blocks = (Nn * 64 + 255) / 256;
    dim3 gemm_grid(2, (Nn + 127) / 128);   // 2 x 391
    dim3 head_grid(2, (Tt + 127) / 128);   // 2 x 79

    // ---- layer 1: aggregate x first (agg(xW) == (agg x)W), then GEMM ----
    k_agg_t<32><<<agg_blocks, 256>>>(x, p_aggx);
    k_gemm<<<gemm_grid, 256>>>(p_aggx, W1, p_hw, Nn, Dd);
    k_stats_partial<<<STATS_BLOCKS, 256>>>();
    k_stats_reduce<<<1, 512>>>();
    k_bn_relu<<<bn_blocks, 256>>>(g1, be1);

    // ---- layer 2 ----
    k_agg_t<64><<<agg_blocks, 256>>>(p_h, p_agg);
    k_gemm<<<gemm_grid, 256>>>(p_agg, W2, p_hw, Nn, Hh);
    k_stats_partial<<<STATS_BLOCKS, 256>>>();
    k_stats_reduce<<<1, 512>>>();
    k_bn_relu<<<bn_blocks, 256>>>(g2, be2);

    // ---- layer 3 ----
    k_agg_t<64><<<agg_blocks, 256>>>(p_h, p_agg);
    k_gemm<<<gemm_grid, 256>>>(p_agg, W3, p_hw, Nn, Hh);
    k_stats_partial<<<STATS_BLOCKS, 256>>>();
    k_stats_reduce<<<1, 512>>>();
    k_bn_relu<<<bn_blocks, 256>>>(g3, be3);

    // ---- head ----
    k_gather<<<(Tt * 64 + 255) / 256, 256>>>(train);
    k_gemm<<<head_grid, 256>>>(p_gath, Wl, p_hw, Tt, Hh);
    k_out<<<(Tt * 32 + 255) / 256, 256>>>(bl, Wf, bf, out);
}

// round 7
// speedup vs baseline: 2.0770x; 1.5485x over previous
#include <cuda_runtime.h>
#include <cuda_bf16.h>
#include <mma.h>
#include <cstdint>

using namespace nvcuda;

#define Nn 50000
#define Ee 800000
#define Dd 128
#define Hh 256
#define Tt 10000
#define EPSV 1e-5f
#define STATS_BLOCKS 200
#define SCAN_BLOCKS 196
#define NPAD 50048   // 391 * 128

// ---------------- scratch ----------------
__device__ float g_disqrt[Nn];
__device__ int   g_cnt[Nn];
__device__ int   g_off[Nn + 1];
__device__ int   g_cursor[Nn];
__device__ int   g_bsum[SCAN_BLOCKS];
__device__ int   g_csrc[Ee];
__device__ float g_cnorm[Ee];
__device__ float g_hw[(size_t)NPAD * Hh];      // GEMM output (fp32)
__device__ float g_part[STATS_BLOCKS * 2 * Hh];
__device__ float g_stats[2 * Hh];
__device__ __nv_bfloat16 g_ahi[(size_t)Nn * Hh];   // aggregated activations hi
__device__ __nv_bfloat16 g_alo[(size_t)Nn * Hh];   // aggregated activations lo
__device__ __nv_bfloat16 g_ghi[(size_t)Tt * Hh];   // gathered train rows hi
__device__ __nv_bfloat16 g_glo[(size_t)Tt * Hh];   // gathered train rows lo
__device__ __nv_bfloat16 g_whi[4 * Hh * Hh];       // split weights hi
__device__ __nv_bfloat16 g_wlo[4 * Hh * Hh];       // split weights lo

// ---------------- helpers ----------------
__device__ __forceinline__ void cp16(uint32_t dst, const void* src, int bytes) {
    asm volatile("cp.async.cg.shared.global [%0], [%1], 16, %2;"
                 :: "r"(dst), "l"(src), "r"(bytes) : "memory");
}
#define CP_COMMIT() asm volatile("cp.async.commit_group;" ::: "memory")
#define CP_WAIT1()  asm volatile("cp.async.wait_group 1;" ::: "memory")
#define CP_WAIT0()  asm volatile("cp.async.wait_group 0;" ::: "memory")

// ---------------- graph preprocessing ----------------
__global__ void k_zero_cnt() {
    int i = blockIdx.x * blockDim.x + threadIdx.x;
    if (i < Nn) g_cnt[i] = 0;
}
__global__ void k_count(const int* __restrict__ row) {
    int e = blockIdx.x * blockDim.x + threadIdx.x;
    if (e < Ee) atomicAdd(&g_cnt[row[e]], 1);
}
__global__ void k_disqrt() {
    int i = blockIdx.x * blockDim.x + threadIdx.x;
    if (i < Nn) g_disqrt[i] = rsqrtf((float)g_cnt[i] + 1.0f);
}
__global__ void k_scan1() {
    int t = threadIdx.x, b = blockIdx.x;
    int i = b * 256 + t;
    int v = (i < Nn) ? g_cnt[i] : 0;
    int lane = t & 31, w = t >> 5;
    int x = v;
#pragma unroll
    for (int o = 1; o < 32; o <<= 1) {
        int y = __shfl_up_sync(0xffffffffu, x, o);
        if (lane >= o) x += y;
    }
    __shared__ int wsum[8];
    if (lane == 31) wsum[w] = x;
    __syncthreads();
    if (w == 0) {
        int s = (lane < 8) ? wsum[lane] : 0;
#pragma unroll
        for (int o = 1; o < 8; o <<= 1) {
            int y = __shfl_up_sync(0xffffffffu, s, o);
            if (lane >= o) s += y;
        }
        if (lane < 8) wsum[lane] = s;
    }
    __syncthreads();
    int incl = x + (w > 0 ? wsum[w - 1] : 0);
    if (i < Nn) g_off[i] = incl - v;
    if (t == 255) g_bsum[b] = incl;
}
__global__ void k_scan2() {
    int t = threadIdx.x;
    int v = (t < SCAN_BLOCKS) ? g_bsum[t] : 0;
    int lane = t & 31, w = t >> 5;
    int x = v;
#pragma unroll
    for (int o = 1; o < 32; o <<= 1) {
        int y = __shfl_up_sync(0xffffffffu, x, o);
        if (lane >= o) x += y;
    }
    __shared__ int wsum[8];
    if (lane == 31) wsum[w] = x;
    __syncthreads();
    if (w == 0) {
        int s = (lane < 8) ? wsum[lane] : 0;
#pragma unroll
        for (int o = 1; o < 8; o <<= 1) {
            int y = __shfl_up_sync(0xffffffffu, s, o);
            if (lane >= o) s += y;
        }
        if (lane < 8) wsum[lane] = s;
    }
    __syncthreads();
    int incl = x + (w > 0 ? wsum[w - 1] : 0);
    if (t < SCAN_BLOCKS) g_bsum[t] = incl - v;
}
__global__ void k_scan3() {
    int t = threadIdx.x, b = blockIdx.x;
    int i = b * 256 + t;
    if (i < Nn) {
        int off = g_off[i] + g_bsum[b];
        g_off[i] = off;
        g_cursor[i] = off;
    }
    if (i == 0) g_off[Nn] = Ee;
}
__global__ void k_scatter(const int* __restrict__ row, const int* __restrict__ col) {
    int e = blockIdx.x * blockDim.x + threadIdx.x;
    if (e < Ee) {
        int d = row[e];
        int s = col[e];
        int pos = atomicAdd(&g_cursor[d], 1);
        g_csrc[pos] = s;
        g_cnorm[pos] = g_disqrt[d] * g_disqrt[s];
    }
}

// ---------------- weight bf16 split ----------------
__global__ void k_wsplit(const float* __restrict__ W, int total,
                         __nv_bfloat16* __restrict__ hi, __nv_bfloat16* __restrict__ lo) {
    int idx = blockIdx.x * blockDim.x + threadIdx.x;
    if (idx >= total) return;
    float v = W[idx];
    __nv_bfloat16 h = __float2bfloat16_rn(v);
    hi[idx] = h;
    lo[idx] = __float2bfloat16_rn(v - __bfloat162float(h));
}

// ---------------- aggregation (optionally fused BN+ReLU of producer) ----------------
// warp per destination node; emits bf16 hi/lo pairs for the GEMM.
template <int COLS, bool BN>
__global__ void k_agg(const float* __restrict__ src,
                      const float* __restrict__ gamma, const float* __restrict__ beta,
                      __nv_bfloat16* __restrict__ dhi, __nv_bfloat16* __restrict__ dlo) {
    constexpr int Q = COLS / 128;
    int warp = (blockIdx.x * blockDim.x + threadIdx.x) >> 5;
    int lane = threadIdx.x & 31;
    if (warp >= Nn) return;

    float scale[Q][4], shift[Q][4];
    if (BN) {
        const float invN = 1.0f / (float)Nn;
#pragma unroll
        for (int q = 0; q < Q; q++)
#pragma unroll
            for (int k = 0; k < 4; k++) {
                int j = q * 128 + lane * 4 + k;
                float mu = g_stats[j] * invN;
                float var = fmaxf(g_stats[Hh + j] * invN - mu * mu, 0.0f);
                float sc = gamma[j] * rsqrtf(var + EPSV);
                scale[q][k] = sc;
                shift[q][k] = beta[j] - mu * sc;
            }
    }

    const float4* s4 = (const float4*)src;
    float dsq = g_disqrt[warp];
    float sl = dsq * dsq;

    float acc[Q][4];
#pragma unroll
    for (int q = 0; q < Q; q++) {
        float4 v = s4[(size_t)warp * (Q * 32) + q * 32 + lane];
        float t[4] = {v.x, v.y, v.z, v.w};
#pragma unroll
        for (int k = 0; k < 4; k++) {
            float u = BN ? fmaxf(fmaf(t[k], scale[q][k], shift[q][k]), 0.0f) : t[k];
            acc[q][k] = u * sl;
        }
    }
    int e0 = g_off[warp], e1 = g_off[warp + 1];
    for (int e = e0; e < e1; e++) {
        int s = g_csrc[e];
        float nm = g_cnorm[e];
#pragma unroll
        for (int q = 0; q < Q; q++) {
            float4 v = s4[(size_t)s * (Q * 32) + q * 32 + lane];
            float t[4] = {v.x, v.y, v.z, v.w};
#pragma unroll
            for (int k = 0; k < 4; k++) {
                float u = BN ? fmaxf(fmaf(t[k], scale[q][k], shift[q][k]), 0.0f) : t[k];
                acc[q][k] = fmaf(u, nm, acc[q][k]);
            }
        }
    }
#pragma unroll
    for (int q = 0; q < Q; q++) {
        size_t base = (size_t)warp * COLS + q * 128 + lane * 4;
        float h[4], l[4];
#pragma unroll
        for (int k = 0; k < 4; k++) {
            __nv_bfloat16 hb = __float2bfloat16_rn(acc[q][k]);
            h[k] = __bfloat162float(hb);
            l[k] = acc[q][k] - h[k];
        }
        *(__nv_bfloat162*)(dhi + base) = __floats2bfloat162_rn(h[0], h[1]);
        *(__nv_bfloat162*)(dhi + base + 2) = __floats2bfloat162_rn(h[2], h[3]);
        *(__nv_bfloat162*)(dlo + base) = __floats2bfloat162_rn(l[0], l[1]);
        *(__nv_bfloat162*)(dlo + base + 2) = __floats2bfloat162_rn(l[2], l[3]);
    }
}

// ---------------- 3xBF16 wmma GEMM, cp.async double buffered, BK=32 ----------------
#define GBK 32
#define ALD 40    // GBK + 8
#define BLD 136   // 128 + 8

using AFrag = wmma::fragment<wmma::matrix_a, 16, 16, 16, __nv_bfloat16, wmma::row_major>;
using BFrag = wmma::fragment<wmma::matrix_b, 16, 16, 16, __nv_bfloat16, wmma::row_major>;
using CFrag = wmma::fragment<wmma::accumulator, 16, 16, 16, float>;

#define SMEM_GEMM ((2 * 128 * ALD * 2 + 2 * GBK * BLD * 2) * 2)  // bytes = 75776

__global__ __launch_bounds__(256) void k_gemm(const __nv_bfloat16* __restrict__ Ahi,
                                              const __nv_bfloat16* __restrict__ Alo,
                                              const __nv_bfloat16* __restrict__ Bhi,
                                              const __nv_bfloat16* __restrict__ Blo,
                                              float* __restrict__ C, int M, int K) {
    extern __shared__ __nv_bfloat16 sm[];
    __nv_bfloat16* AH = sm;                          // [2][128][ALD]
    __nv_bfloat16* AL = AH + 2 * 128 * ALD;
    __nv_bfloat16* BH = AL + 2 * 128 * ALD;          // [2][GBK][BLD]
    __nv_bfloat16* BL = BH + 2 * GBK * BLD;

    const int tid = threadIdx.x;
    const int warp = tid >> 5;
    const int rowBase = blockIdx.y * 128;
    const int colBase = blockIdx.x * 128;
    const int wm = warp & 3;
    const int wn = warp >> 2;

    CFrag c[2][4];
#pragma unroll
    for (int i = 0; i < 2; i++)
#pragma unroll
        for (int j = 0; j < 4; j++) wmma::fill_fragment(c[i][j], 0.0f);

    auto load_stage = [&](int buf, int k0) {
#pragma unroll
        for (int t = 0; t < 2; t++) {
            int id = tid + t * 256;       // 0..511
            int r = id >> 2;              // 0..127
            int cc = (id & 3) * 8;        // bf16 col: 0,8,16,24
            int grow = rowBase + r;
            size_t gofs = (size_t)(grow < M ? grow : 0) * K + k0 + cc;
            int bytes = grow < M ? 16 : 0;
            cp16((uint32_t)__cvta_generic_to_shared(AH + ((size_t)buf * 128 + r) * ALD + cc),
                 Ahi + gofs, bytes);
            cp16((uint32_t)__cvta_generic_to_shared(AL + ((size_t)buf * 128 + r) * ALD + cc),
                 Alo + gofs, bytes);
        }
#pragma unroll
        for (int t = 0; t < 2; t++) {
            int id = tid + t * 256;       // 0..511
            int kr = id >> 4;             // 0..31
            int nc = (id & 15) * 8;       // 0..120
            size_t gofs = (size_t)(k0 + kr) * Hh + colBase + nc;
            cp16((uint32_t)__cvta_generic_to_shared(BH + ((size_t)buf * GBK + kr) * BLD + nc),
                 Bhi + gofs, 16);
            cp16((uint32_t)__cvta_generic_to_shared(BL + ((size_t)buf * GBK + kr) * BLD + nc),
                 Blo + gofs, 16);
        }
    };

    const int NC = K >> 5;
    load_stage(0, 0);
    CP_COMMIT();

    for (int cidx = 0; cidx < NC; cidx++) {
        int buf = cidx & 1;
        if (cidx + 1 < NC) {
            load_stage(buf ^ 1, (cidx + 1) << 5);
            CP_COMMIT();
            CP_WAIT1();
        } else {
            CP_WAIT0();
        }
        __syncthreads();

#pragma unroll
        for (int ks = 0; ks < 2; ks++) {
            AFrag ah[2], al[2];
            BFrag bh[4], bl[4];
#pragma unroll
            for (int i = 0; i < 2; i++) {
                const __nv_bfloat16* pa = AH + ((size_t)buf * 128 + wm * 32 + i * 16) * ALD + ks * 16;
                wmma::load_matrix_sync(ah[i], pa, ALD);
                wmma::load_matrix_sync(al[i], pa + 2 * 128 * ALD, ALD);  // AL at fixed offset
            }
#pragma unroll
            for (int j = 0; j < 4; j++) {
                const __nv_bfloat16* pb = BH + ((size_t)buf * GBK + ks * 16) * BLD + wn * 64 + j * 16;
                wmma::load_matrix_sync(bh[j], pb, BLD);
                wmma::load_matrix_sync(bl[j], pb + 2 * GBK * BLD, BLD);  // BL at fixed offset
            }
#pragma unroll
            for (int i = 0; i < 2; i++)
#pragma unroll
                for (int j = 0; j < 4; j++) {
                    wmma::mma_sync(c[i][j], ah[i], bh[j], c[i][j]);
                    wmma::mma_sync(c[i][j], ah[i], bl[j], c[i][j]);
                    wmma::mma_sync(c[i][j], al[i], bh[j], c[i][j]);
                }
        }
        __syncthreads();
    }

#pragma unroll
    for (int i = 0; i < 2; i++)
#pragma unroll
        for (int j = 0; j < 4; j++) {
            int grow = rowBase + wm * 32 + i * 16;   // C padded to NPAD rows
            wmma::store_matrix_sync(C + (size_t)grow * Hh + colBase + wn * 64 + j * 16,
                                    c[i][j], Hh, wmma::mem_row_major);
        }
}

// ---------------- BatchNorm stats (on g_hw) ----------------
__global__ void k_stats_partial() {
    int j = threadIdx.x;
    float s = 0.f, s2 = 0.f;
    for (int r = blockIdx.x; r < Nn; r += gridDim.x) {
        float v = g_hw[(size_t)r * Hh + j];
        s += v;
        s2 += v * v;
    }
    g_part[blockIdx.x * 2 * Hh + j] = s;
    g_part[blockIdx.x * 2 * Hh + Hh + j] = s2;
}
__global__ void k_stats_reduce() {
    int j = blockIdx.x * blockDim.x + threadIdx.x;
    if (j >= 2 * Hh) return;
    float s = 0.f;
    for (int b = 0; b < STATS_BLOCKS; b++) s += g_part[b * 2 * Hh + j];
    g_stats[j] = s;
}

// ---------------- head: gather + BN3 + relu + bf16 split ----------------
__global__ void k_gather_bn(const int* __restrict__ train,
                            const float* __restrict__ gamma, const float* __restrict__ beta) {
    int idx = blockIdx.x * blockDim.x + threadIdx.x;
    if (idx >= Tt * 64) return;
    int t = idx >> 6, cq = idx & 63;
    int node = train[t];
    float4 v = ((const float4*)g_hw)[(size_t)node * 64 + cq];
    const float invN = 1.0f / (float)Nn;
    float tv[4] = {v.x, v.y, v.z, v.w};
    float h[4], l[4];
#pragma unroll
    for (int k = 0; k < 4; k++) {
        int j = cq * 4 + k;
        float mu = g_stats[j] * invN;
        float var = fmaxf(g_stats[Hh + j] * invN - mu * mu, 0.0f);
        float sc = gamma[j] * rsqrtf(var + EPSV);
        float u = fmaxf(fmaf(tv[k], sc, beta[j] - mu * sc), 0.0f);
        __nv_bfloat16 hb = __float2bfloat16_rn(u);
        h[k] = __bfloat162float(hb);
        l[k] = u - h[k];
    }
    size_t base = (size_t)t * Hh + cq * 4;
    *(__nv_bfloat162*)(g_ghi + base) = __floats2bfloat162_rn(h[0], h[1]);
    *(__nv_bfloat162*)(g_ghi + base + 2) = __floats2bfloat162_rn(h[2], h[3]);
    *(__nv_bfloat162*)(g_glo + base) = __floats2bfloat162_rn(l[0], l[1]);
    *(__nv_bfloat162*)(g_glo + base + 2) = __floats2bfloat162_rn(l[2], l[3]);
}

__global__ void k_out(const float* __restrict__ bl, const float* __restrict__ Wf,
                      const float* __restrict__ bf, float* __restrict__ out) {
    int warp = (blockIdx.x * blockDim.x + threadIdx.x) >> 5;
    int lane = threadIdx.x & 31;
    if (warp >= Tt) return;
    float acc = 0.f;
    const float* hp = g_hw + (size_t)warp * Hh;
#pragma unroll
    for (int j0 = 0; j0 < Hh; j0 += 32) {
        int j = j0 + lane;
        float v = fmaxf(hp[j] + bl[j], 0.0f);
        acc = fmaf(v, Wf[j], acc);
    }
#pragma unroll
    for (int o = 16; o > 0; o >>= 1) acc += __shfl_xor_sync(0xffffffffu, acc, o);
    if (lane == 0) out[warp] = acc + bf[0];
}

// ---------------- launch ----------------
extern "C" void kernel_launch(void* const* d_in, const int* in_sizes, int n_in,
                              void* d_out, int out_size) {
    const float* x = (const float*)d_in[0];
    const int* ei = (const int*)d_in[1];
    const int* train = (const int*)d_in[2];
    const float* W1 = (const float*)d_in[3];
    const float* W2 = (const float*)d_in[5];
    const float* W3 = (const float*)d_in[7];
    const float* g1 = (const float*)d_in[9];
    const float* be1 = (const float*)d_in[10];
    const float* g2 = (const float*)d_in[11];
    const float* be2 = (const float*)d_in[12];
    const float* g3 = (const float*)d_in[13];
    const float* be3 = (const float*)d_in[14];
    const float* Wl = (const float*)d_in[15];
    const float* bl = (const float*)d_in[16];
    const float* Wf = (const float*)d_in[17];
    const float* bf = (const float*)d_in[18];
    float* out = (float*)d_out;

    const int* row = ei;
    const int* col = ei + Ee;

    float* p_hw;
    __nv_bfloat16 *p_ahi, *p_alo, *p_ghi, *p_glo, *p_whi, *p_wlo;
    cudaGetSymbolAddress((void**)&p_hw, g_hw);
    cudaGetSymbolAddress((void**)&p_ahi, g_ahi);
    cudaGetSymbolAddress((void**)&p_alo, g_alo);
    cudaGetSymbolAddress((void**)&p_ghi, g_ghi);
    cudaGetSymbolAddress((void**)&p_glo, g_glo);
    cudaGetSymbolAddress((void**)&p_whi, g_whi);
    cudaGetSymbolAddress((void**)&p_wlo, g_wlo);

    cudaFuncSetAttribute(k_gemm, cudaFuncAttributeMaxDynamicSharedMemorySize, SMEM_GEMM);

    // ---- graph preprocessing ----
    k_zero_cnt<<<(Nn + 255) / 256, 256>>>();
    k_count<<<(Ee + 255) / 256, 256>>>(row);
    k_disqrt<<<(Nn + 255) / 256, 256>>>();
    k_scan1<<<SCAN_BLOCKS, 256>>>();
    k_scan2<<<1, 256>>>();
    k_scan3<<<SCAN_BLOCKS, 256>>>();
    k_scatter<<<(Ee + 255) / 256, 256>>>(row, col);

    // ---- weight splits ----
    k_wsplit<<<(Dd * Hh + 255) / 256, 256>>>(W1, Dd * Hh, p_whi + 0 * Hh * Hh, p_wlo + 0 * Hh * Hh);
    k_wsplit<<<(Hh * Hh + 255) / 256, 256>>>(W2, Hh * Hh, p_whi + 1 * Hh * Hh, p_wlo + 1 * Hh * Hh);
    k_wsplit<<<(Hh * Hh + 255) / 256, 256>>>(W3, Hh * Hh, p_whi + 2 * Hh * Hh, p_wlo + 2 * Hh * Hh);
    k_wsplit<<<(Hh * Hh + 255) / 256, 256>>>(Wl, Hh * Hh, p_whi + 3 * Hh * Hh, p_wlo + 3 * Hh * Hh);

    const int agg_blocks = (Nn * 32 + 255) / 256;
    dim3 gemm_grid(2, (Nn + 127) / 128);
    dim3 head_grid(2, (Tt + 127) / 128);

    // ---- layer 1: agg(x) -> bf16 split; GEMM K=128 ----
    k_agg<128, false><<<agg_blocks, 256>>>(x, nullptr, nullptr, p_ahi, p_alo);
    k_gemm<<<gemm_grid, 256, SMEM_GEMM>>>(p_ahi, p_alo, p_whi, p_wlo, p_hw, Nn, Dd);
    k_stats_partial<<<STATS_BLOCKS, 256>>>();
    k_stats_reduce<<<1, 512>>>();

    // ---- layer 2: agg(bn1+relu(g_hw)) -> bf16; GEMM K=256 ----
    k_agg<256, true><<<agg_blocks, 256>>>(p_hw, g1, be1, p_ahi, p_alo);
    k_gemm<<<gemm_grid, 256, SMEM_GEMM>>>(p_ahi, p_alo, p_whi + 1 * Hh * Hh, p_wlo + 1 * Hh * Hh,
                                          p_hw, Nn, Hh);
    k_stats_partial<<<STATS_BLOCKS, 256>>>();
    k_stats_reduce<<<1, 512>>>();

    // ---- layer 3 ----
    k_agg<256, true><<<agg_blocks, 256>>>(p_hw, g2, be2, p_ahi, p_alo);
    k_gemm<<<gemm_grid, 256, SMEM_GEMM>>>(p_ahi, p_alo, p_whi + 2 * Hh * Hh, p_wlo + 2 * Hh * Hh,
                                          p_hw, Nn, Hh);
    k_stats_partial<<<STATS_BLOCKS, 256>>>();
    k_stats_reduce<<<1, 512>>>();

    // ---- head: gather+bn3+relu -> bf16; Wl GEMM; fused relu+Wf dot ----
    k_gather_bn<<<(Tt * 64 + 255) / 256, 256>>>(train, g3, be3);
    k_gemm<<<head_grid, 256, SMEM_GEMM>>>(p_ghi, p_glo, p_whi + 3 * Hh * Hh, p_wlo + 3 * Hh * Hh,
                                          p_hw, Tt, Hh);
    k_out<<<(Tt * 32 + 255) / 256, 256>>>(bl, Wf, bf, out);
}

// round 8
// speedup vs baseline: 2.9473x; 1.4190x over previous
#include <cuda_runtime.h>
#include <cuda_bf16.h>
#include <mma.h>
#include <cstdint>

using namespace nvcuda;

#define Nn 50000
#define Ee 800000
#define Dd 128
#define Hh 256
#define Tt 10000
#define EPSV 1e-5f
#define SCAN_BLOCKS 196
#define NPAD 50048   // 391 * 128

// ---------------- scratch ----------------
__device__ float g_disqrt[Nn];
__device__ int   g_cnt[Nn];
__device__ int   g_off[Nn + 1];
__device__ int   g_cursor[Nn];
__device__ int   g_bsum[SCAN_BLOCKS];
__device__ int   g_csrc[Ee];
__device__ float g_cnorm[Ee];
__device__ float g_hw[(size_t)NPAD * Hh];      // GEMM output (fp32)
__device__ float g_stats4[4][2 * Hh];          // per-layer [sum|sumsq] slots
__device__ __nv_bfloat16 g_ahi[(size_t)Nn * Hh];
__device__ __nv_bfloat16 g_alo[(size_t)Nn * Hh];
__device__ __nv_bfloat16 g_ghi[(size_t)Tt * Hh];
__device__ __nv_bfloat16 g_glo[(size_t)Tt * Hh];
__device__ __nv_bfloat16 g_whi[4 * Hh * Hh];
__device__ __nv_bfloat16 g_wlo[4 * Hh * Hh];

// ---------------- helpers ----------------
__device__ __forceinline__ void cp16(uint32_t dst, const void* src, int bytes) {
    asm volatile("cp.async.cg.shared.global [%0], [%1], 16, %2;"
                 :: "r"(dst), "l"(src), "r"(bytes) : "memory");
}
#define CP_COMMIT() asm volatile("cp.async.commit_group;" ::: "memory")
#define CP_WAIT1()  asm volatile("cp.async.wait_group 1;" ::: "memory")
#define CP_WAIT0()  asm volatile("cp.async.wait_group 0;" ::: "memory")

// ---------------- graph preprocessing ----------------
__global__ void k_zero_init() {
    int i = blockIdx.x * blockDim.x + threadIdx.x;
    if (i < Nn) g_cnt[i] = 0;
    if (i < 4 * 2 * Hh) ((float*)g_stats4)[i] = 0.0f;
}
__global__ void k_count(const int* __restrict__ row) {
    int e = blockIdx.x * blockDim.x + threadIdx.x;
    if (e < Ee) atomicAdd(&g_cnt[row[e]], 1);
}
__global__ void k_scan1() {   // also computes disqrt
    int t = threadIdx.x, b = blockIdx.x;
    int i = b * 256 + t;
    int v = (i < Nn) ? g_cnt[i] : 0;
    if (i < Nn) g_disqrt[i] = rsqrtf((float)v + 1.0f);
    int lane = t & 31, w = t >> 5;
    int x = v;
#pragma unroll
    for (int o = 1; o < 32; o <<= 1) {
        int y = __shfl_up_sync(0xffffffffu, x, o);
        if (lane >= o) x += y;
    }
    __shared__ int wsum[8];
    if (lane == 31) wsum[w] = x;
    __syncthreads();
    if (w == 0) {
        int s = (lane < 8) ? wsum[lane] : 0;
#pragma unroll
        for (int o = 1; o < 8; o <<= 1) {
            int y = __shfl_up_sync(0xffffffffu, s, o);
            if (lane >= o) s += y;
        }
        if (lane < 8) wsum[lane] = s;
    }
    __syncthreads();
    int incl = x + (w > 0 ? wsum[w - 1] : 0);
    if (i < Nn) g_off[i] = incl - v;
    if (t == 255) g_bsum[b] = incl;
}
__global__ void k_scan2() {
    int t = threadIdx.x;
    int v = (t < SCAN_BLOCKS) ? g_bsum[t] : 0;
    int lane = t & 31, w = t >> 5;
    int x = v;
#pragma unroll
    for (int o = 1; o < 32; o <<= 1) {
        int y = __shfl_up_sync(0xffffffffu, x, o);
        if (lane >= o) x += y;
    }
    __shared__ int wsum[8];
    if (lane == 31) wsum[w] = x;
    __syncthreads();
    if (w == 0) {
        int s = (lane < 8) ? wsum[lane] : 0;
#pragma unroll
        for (int o = 1; o < 8; o <<= 1) {
            int y = __shfl_up_sync(0xffffffffu, s, o);
            if (lane >= o) s += y;
        }
        if (lane < 8) wsum[lane] = s;
    }
    __syncthreads();
    int incl = x + (w > 0 ? wsum[w - 1] : 0);
    if (t < SCAN_BLOCKS) g_bsum[t] = incl - v;
}
__global__ void k_scan3() {
    int t = threadIdx.x, b = blockIdx.x;
    int i = b * 256 + t;
    if (i < Nn) {
        int off = g_off[i] + g_bsum[b];
        g_off[i] = off;
        g_cursor[i] = off;
    }
    if (i == 0) g_off[Nn] = Ee;
}
__global__ void k_scatter(const int* __restrict__ row, const int* __restrict__ col) {
    int e = blockIdx.x * blockDim.x + threadIdx.x;
    if (e < Ee) {
        int d = row[e];
        int s = col[e];
        int pos = atomicAdd(&g_cursor[d], 1);
        g_csrc[pos] = s;
        g_cnorm[pos] = g_disqrt[d] * g_disqrt[s];
    }
}

// ---------------- all-weights bf16 split (one kernel) ----------------
__global__ void k_wsplit_all(const float* __restrict__ W1, const float* __restrict__ W2,
                             const float* __restrict__ W3, const float* __restrict__ Wl) {
    int idx = blockIdx.x * blockDim.x + threadIdx.x;
    const int S1 = Dd * Hh;            // 32768
    const int SW = Hh * Hh;            // 65536
    const int total = S1 + 3 * SW;
    if (idx >= total) return;
    const float* src;
    int dofs;
    if (idx < S1) { src = W1 + idx; dofs = idx; }
    else {
        int r = idx - S1;
        int which = r / SW, o = r % SW;
        src = (which == 0 ? W2 : which == 1 ? W3 : Wl) + o;
        dofs = (which + 1) * SW + o;   // slots 1,2,3 at offset Hh*Hh
    }
    float v = *src;
    __nv_bfloat16 h = __float2bfloat16_rn(v);
    g_whi[dofs] = h;
    g_wlo[dofs] = __float2bfloat16_rn(v - __bfloat162float(h));
}

// ---------------- aggregation (optionally fused BN+ReLU of producer) ----------------
template <int COLS, bool BN>
__global__ void k_agg(const float* __restrict__ src, const float* __restrict__ stats,
                      const float* __restrict__ gamma, const float* __restrict__ beta,
                      __nv_bfloat16* __restrict__ dhi, __nv_bfloat16* __restrict__ dlo) {
    constexpr int Q = COLS / 128;
    int warp = (blockIdx.x * blockDim.x + threadIdx.x) >> 5;
    int lane = threadIdx.x & 31;
    if (warp >= Nn) return;

    float scale[Q][4], shift[Q][4];
    if (BN) {
        const float invN = 1.0f / (float)Nn;
#pragma unroll
        for (int q = 0; q < Q; q++)
#pragma unroll
            for (int k = 0; k < 4; k++) {
                int j = q * 128 + lane * 4 + k;
                float mu = stats[j] * invN;
                float var = fmaxf(stats[Hh + j] * invN - mu * mu, 0.0f);
                float sc = gamma[j] * rsqrtf(var + EPSV);
                scale[q][k] = sc;
                shift[q][k] = beta[j] - mu * sc;
            }
    }

    const float4* s4 = (const float4*)src;
    float dsq = g_disqrt[warp];
    float sl = dsq * dsq;

    float acc[Q][4];
#pragma unroll
    for (int q = 0; q < Q; q++) {
        float4 v = s4[(size_t)warp * (Q * 32) + q * 32 + lane];
        float t[4] = {v.x, v.y, v.z, v.w};
#pragma unroll
        for (int k = 0; k < 4; k++) {
            float u = BN ? fmaxf(fmaf(t[k], scale[q][k], shift[q][k]), 0.0f) : t[k];
            acc[q][k] = u * sl;
        }
    }
    int e0 = g_off[warp], e1 = g_off[warp + 1];
    for (int e = e0; e < e1; e++) {
        int s = g_csrc[e];
        float nm = g_cnorm[e];
#pragma unroll
        for (int q = 0; q < Q; q++) {
            float4 v = s4[(size_t)s * (Q * 32) + q * 32 + lane];
            float t[4] = {v.x, v.y, v.z, v.w};
#pragma unroll
            for (int k = 0; k < 4; k++) {
                float u = BN ? fmaxf(fmaf(t[k], scale[q][k], shift[q][k]), 0.0f) : t[k];
                acc[q][k] = fmaf(u, nm, acc[q][k]);
            }
        }
    }
#pragma unroll
    for (int q = 0; q < Q; q++) {
        size_t base = (size_t)warp * COLS + q * 128 + lane * 4;
        float h[4], l[4];
#pragma unroll
        for (int k = 0; k < 4; k++) {
            __nv_bfloat16 hb = __float2bfloat16_rn(acc[q][k]);
            h[k] = __bfloat162float(hb);
            l[k] = acc[q][k] - h[k];
        }
        *(__nv_bfloat162*)(dhi + base) = __floats2bfloat162_rn(h[0], h[1]);
        *(__nv_bfloat162*)(dhi + base + 2) = __floats2bfloat162_rn(h[2], h[3]);
        *(__nv_bfloat162*)(dlo + base) = __floats2bfloat162_rn(l[0], l[1]);
        *(__nv_bfloat162*)(dlo + base + 2) = __floats2bfloat162_rn(l[2], l[3]);
    }
}

// ---------------- 3xBF16 wmma GEMM, cp.async double buffered, fused stats ----------------
#define GBK 32
#define ALD 40    // GBK + 8
#define BLD 136   // 128 + 8
#define CLD 132   // epilogue C tile ld

using AFrag = wmma::fragment<wmma::matrix_a, 16, 16, 16, __nv_bfloat16, wmma::row_major>;
using BFrag = wmma::fragment<wmma::matrix_b, 16, 16, 16, __nv_bfloat16, wmma::row_major>;
using CFrag = wmma::fragment<wmma::accumulator, 16, 16, 16, float>;

#define STAGE_BYTES ((2 * 128 * ALD * 2 + 2 * GBK * BLD * 2) * 2)  // 75776
#define CTILE_BYTES (128 * CLD * 4)                                 // 67584
#define SMEM_GEMM (STAGE_BYTES > CTILE_BYTES ? STAGE_BYTES : CTILE_BYTES)

__global__ __launch_bounds__(256) void k_gemm(const __nv_bfloat16* __restrict__ Ahi,
                                              const __nv_bfloat16* __restrict__ Alo,
                                              const __nv_bfloat16* __restrict__ Bhi,
                                              const __nv_bfloat16* __restrict__ Blo,
                                              float* __restrict__ C,
                                              float* __restrict__ stats,
                                              int M, int K) {
    extern __shared__ __nv_bfloat16 sm[];
    __nv_bfloat16* AH = sm;                          // [2][128][ALD]
    __nv_bfloat16* AL = AH + 2 * 128 * ALD;
    __nv_bfloat16* BH = AL + 2 * 128 * ALD;          // [2][GBK][BLD]
    __nv_bfloat16* BL = BH + 2 * GBK * BLD;

    const int tid = threadIdx.x;
    const int warp = tid >> 5;
    const int rowBase = blockIdx.y * 128;
    const int colBase = blockIdx.x * 128;
    const int wm = warp & 3;
    const int wn = warp >> 2;

    CFrag c[2][4];
#pragma unroll
    for (int i = 0; i < 2; i++)
#pragma unroll
        for (int j = 0; j < 4; j++) wmma::fill_fragment(c[i][j], 0.0f);

    auto load_stage = [&](int buf, int k0) {
#pragma unroll
        for (int t = 0; t < 2; t++) {
            int id = tid + t * 256;
            int r = id >> 2;
            int cc = (id & 3) * 8;
            int grow = rowBase + r;
            size_t gofs = (size_t)(grow < M ? grow : 0) * K + k0 + cc;
            int bytes = grow < M ? 16 : 0;
            cp16((uint32_t)__cvta_generic_to_shared(AH + ((size_t)buf * 128 + r) * ALD + cc),
                 Ahi + gofs, bytes);
            cp16((uint32_t)__cvta_generic_to_shared(AL + ((size_t)buf * 128 + r) * ALD + cc),
                 Alo + gofs, bytes);
        }
#pragma unroll
        for (int t = 0; t < 2; t++) {
            int id = tid + t * 256;
            int kr = id >> 4;
            int nc = (id & 15) * 8;
            size_t gofs = (size_t)(k0 + kr) * Hh + colBase + nc;
            cp16((uint32_t)__cvta_generic_to_shared(BH + ((size_t)buf * GBK + kr) * BLD + nc),
                 Bhi + gofs, 16);
            cp16((uint32_t)__cvta_generic_to_shared(BL + ((size_t)buf * GBK + kr) * BLD + nc),
                 Blo + gofs, 16);
        }
    };

    const int NC = K >> 5;
    load_stage(0, 0);
    CP_COMMIT();

    for (int cidx = 0; cidx < NC; cidx++) {
        int buf = cidx & 1;
        if (cidx + 1 < NC) {
            load_stage(buf ^ 1, (cidx + 1) << 5);
            CP_COMMIT();
            CP_WAIT1();
        } else {
            CP_WAIT0();
        }
        __syncthreads();

#pragma unroll
        for (int ks = 0; ks < 2; ks++) {
            AFrag ah[2], al[2];
            BFrag bh[4], bl[4];
#pragma unroll
            for (int i = 0; i < 2; i++) {
                const __nv_bfloat16* pa = AH + ((size_t)buf * 128 + wm * 32 + i * 16) * ALD + ks * 16;
                wmma::load_matrix_sync(ah[i], pa, ALD);
                wmma::load_matrix_sync(al[i], pa + 2 * 128 * ALD, ALD);
            }
#pragma unroll
            for (int j = 0; j < 4; j++) {
                const __nv_bfloat16* pb = BH + ((size_t)buf * GBK + ks * 16) * BLD + wn * 64 + j * 16;
                wmma::load_matrix_sync(bh[j], pb, BLD);
                wmma::load_matrix_sync(bl[j], pb + 2 * GBK * BLD, BLD);
            }
#pragma unroll
            for (int i = 0; i < 2; i++)
#pragma unroll
                for (int j = 0; j < 4; j++) {
                    wmma::mma_sync(c[i][j], ah[i], bh[j], c[i][j]);
                    wmma::mma_sync(c[i][j], ah[i], bl[j], c[i][j]);
                    wmma::mma_sync(c[i][j], al[i], bh[j], c[i][j]);
                }
        }
        __syncthreads();
    }

    // store to gmem
#pragma unroll
    for (int i = 0; i < 2; i++)
#pragma unroll
        for (int j = 0; j < 4; j++) {
            int grow = rowBase + wm * 32 + i * 16;
            wmma::store_matrix_sync(C + (size_t)grow * Hh + colBase + wn * 64 + j * 16,
                                    c[i][j], Hh, wmma::mem_row_major);
        }

    // fused BN stats: stage C tile in smem, column-reduce, atomicAdd
    if (stats) {
        float* ct = (float*)sm;   // 128 x CLD (mainloop smem dead now)
#pragma unroll
        for (int i = 0; i < 2; i++)
#pragma unroll
            for (int j = 0; j < 4; j++)
                wmma::store_matrix_sync(ct + (size_t)(wm * 32 + i * 16) * CLD + wn * 64 + j * 16,
                                        c[i][j], CLD, wmma::mem_row_major);
        __syncthreads();
        int col = tid & 127;
        int half = tid >> 7;     // 0 or 1: rows [0,64) or [64,128)
        const float* p = ct + (size_t)half * 64 * CLD + col;
        float s = 0.f, s2 = 0.f;
#pragma unroll 8
        for (int r = 0; r < 64; r++) {
            float v = p[(size_t)r * CLD];
            s += v;
            s2 = fmaf(v, v, s2);
        }
        atomicAdd(&stats[colBase + col], s);
        atomicAdd(&stats[Hh + colBase + col], s2);
    }
}

// ---------------- head: gather + BN3 + relu + bf16 split ----------------
__global__ void k_gather_bn(const int* __restrict__ train, const float* __restrict__ stats,
                            const float* __restrict__ gamma, const float* __restrict__ beta) {
    int idx = blockIdx.x * blockDim.x + threadIdx.x;
    if (idx >= Tt * 64) return;
    int t = idx >> 6, cq = idx & 63;
    int node = train[t];
    float4 v = ((const float4*)g_hw)[(size_t)node * 64 + cq];
    const float invN = 1.0f / (float)Nn;
    float tv[4] = {v.x, v.y, v.z, v.w};
    float h[4], l[4];
#pragma unroll
    for (int k = 0; k < 4; k++) {
        int j = cq * 4 + k;
        float mu = stats[j] * invN;
        float var = fmaxf(stats[Hh + j] * invN - mu * mu, 0.0f);
        float sc = gamma[j] * rsqrtf(var + EPSV);
        float u = fmaxf(fmaf(tv[k], sc, beta[j] - mu * sc), 0.0f);
        __nv_bfloat16 hb = __float2bfloat16_rn(u);
        h[k] = __bfloat162float(hb);
        l[k] = u - h[k];
    }
    size_t base = (size_t)t * Hh + cq * 4;
    *(__nv_bfloat162*)(g_ghi + base) = __floats2bfloat162_rn(h[0], h[1]);
    *(__nv_bfloat162*)(g_ghi + base + 2) = __floats2bfloat162_rn(h[2], h[3]);
    *(__nv_bfloat162*)(g_glo + base) = __floats2bfloat162_rn(l[0], l[1]);
    *(__nv_bfloat162*)(g_glo + base + 2) = __floats2bfloat162_rn(l[2], l[3]);
}

__global__ void k_out(const float* __restrict__ bl, const float* __restrict__ Wf,
                      const float* __restrict__ bf, float* __restrict__ out) {
    int warp = (blockIdx.x * blockDim.x + threadIdx.x) >> 5;
    int lane = threadIdx.x & 31;
    if (warp >= Tt) return;
    float acc = 0.f;
    const float* hp = g_hw + (size_t)warp * Hh;
#pragma unroll
    for (int j0 = 0; j0 < Hh; j0 += 32) {
        int j = j0 + lane;
        float v = fmaxf(hp[j] + bl[j], 0.0f);
        acc = fmaf(v, Wf[j], acc);
    }
#pragma unroll
    for (int o = 16; o > 0; o >>= 1) acc += __shfl_xor_sync(0xffffffffu, acc, o);
    if (lane == 0) out[warp] = acc + bf[0];
}

// ---------------- launch ----------------
extern "C" void kernel_launch(void* const* d_in, const int* in_sizes, int n_in,
                              void* d_out, int out_size) {
    const float* x = (const float*)d_in[0];
    const int* ei = (const int*)d_in[1];
    const int* train = (const int*)d_in[2];
    const float* W1 = (const float*)d_in[3];
    const float* W2 = (const float*)d_in[5];
    const float* W3 = (const float*)d_in[7];
    const float* g1 = (const float*)d_in[9];
    const float* be1 = (const float*)d_in[10];
    const float* g2 = (const float*)d_in[11];
    const float* be2 = (const float*)d_in[12];
    const float* g3 = (const float*)d_in[13];
    const float* be3 = (const float*)d_in[14];
    const float* Wl = (const float*)d_in[15];
    const float* bl = (const float*)d_in[16];
    const float* Wf = (const float*)d_in[17];
    const float* bf = (const float*)d_in[18];
    float* out = (float*)d_out;

    const int* row = ei;
    const int* col = ei + Ee;

    float *p_hw, *p_stats;
    __nv_bfloat16 *p_ahi, *p_alo, *p_ghi, *p_glo, *p_whi, *p_wlo;
    cudaGetSymbolAddress((void**)&p_hw, g_hw);
    cudaGetSymbolAddress((void**)&p_stats, g_stats4);
    cudaGetSymbolAddress((void**)&p_ahi, g_ahi);
    cudaGetSymbolAddress((void**)&p_alo, g_alo);
    cudaGetSymbolAddress((void**)&p_ghi, g_ghi);
    cudaGetSymbolAddress((void**)&p_glo, g_glo);
    cudaGetSymbolAddress((void**)&p_whi, g_whi);
    cudaGetSymbolAddress((void**)&p_wlo, g_wlo);

    cudaFuncSetAttribute(k_gemm, cudaFuncAttributeMaxDynamicSharedMemorySize, SMEM_GEMM);

    // ---- graph preprocessing ----
    k_zero_init<<<(Nn + 255) / 256, 256>>>();
    k_count<<<(Ee + 255) / 256, 256>>>(row);
    k_scan1<<<SCAN_BLOCKS, 256>>>();
    k_scan2<<<1, 256>>>();
    k_scan3<<<SCAN_BLOCKS, 256>>>();
    k_scatter<<<(Ee + 255) / 256, 256>>>(row, col);
    k_wsplit_all<<<(Dd * Hh + 3 * Hh * Hh + 255) / 256, 256>>>(W1, W2, W3, Wl);

    const int agg_blocks = (Nn * 32 + 255) / 256;
    dim3 gemm_grid(2, (Nn + 127) / 128);
    dim3 head_grid(2, (Tt + 127) / 128);
    float* st0 = p_stats + 0 * 2 * Hh;
    float* st1 = p_stats + 1 * 2 * Hh;
    float* st2 = p_stats + 2 * 2 * Hh;

    // ---- layer 1 ----
    k_agg<128, false><<<agg_blocks, 256>>>(x, nullptr, nullptr, nullptr, p_ahi, p_alo);
    k_gemm<<<gemm_grid, 256, SMEM_GEMM>>>(p_ahi, p_alo, p_whi, p_wlo, p_hw, st0, Nn, Dd);

    // ---- layer 2 ----
    k_agg<256, true><<<agg_blocks, 256>>>(p_hw, st0, g1, be1, p_ahi, p_alo);
    k_gemm<<<gemm_grid, 256, SMEM_GEMM>>>(p_ahi, p_alo, p_whi + 1 * Hh * Hh, p_wlo + 1 * Hh * Hh,
                                          p_hw, st1, Nn, Hh);

    // ---- layer 3 ----
    k_agg<256, true><<<agg_blocks, 256>>>(p_hw, st1, g2, be2, p_ahi, p_alo);
    k_gemm<<<gemm_grid, 256, SMEM_GEMM>>>(p_ahi, p_alo, p_whi + 2 * Hh * Hh, p_wlo + 2 * Hh * Hh,
                                          p_hw, st2, Nn, Hh);

    // ---- head ----
    k_gather_bn<<<(Tt * 64 + 255) / 256, 256>>>(train, st2, g3, be3);
    k_gemm<<<head_grid, 256, SMEM_GEMM>>>(p_ghi, p_glo, p_whi + 3 * Hh * Hh, p_wlo + 3 * Hh * Hh,
                                          p_hw, nullptr, Tt, Hh);
    k_out<<<(Tt * 32 + 255) / 256, 256>>>(bl, Wf, bf, out);
}